// round 15
// baseline (speedup 1.0000x reference)
#include <cuda_runtime.h>
#include <cuda_fp16.h>
#include <cstdint>
#include <cmath>

// Problem constants
#define B_   8
#define T_   2048
#define C_   1024
#define M_   (B_*T_)       // 16384
#define BTC  (B_*T_*C_)    // 16777216
#define BC_  (B_*C_)       // 8192

// Chunked scan
#define NCH 32
#define CL  (T_/NCH)       // 64

// ---------------------------------------------------------------------------
// Scratch (__device__ globals; no cudaMalloc allowed)
// ---------------------------------------------------------------------------
__device__ __half g_xk[BTC];
__device__ __half g_xv[BTC];
__device__ __half g_xr[BTC];
__device__ __half g_W16[3][C_*C_];
__device__ __half g_k16[BTC], g_v16[BTC], g_r16[BTC];
// scan scratch
__device__ float g_chA[NCH][BC_], g_chB[NCH][BC_], g_chP[NCH][BC_];
__device__ float g_inA[NCH][BC_], g_inB[NCH][BC_], g_inP[NCH][BC_];
__device__ float g_psum[NCH][BC_];
__device__ float g_ylast[BC_];
__device__ float g_z[BC_];

// ---------------------------------------------------------------------------
// Generic-PTX helpers (sm_80-class; safe for the harness's compute_103 build)
// ---------------------------------------------------------------------------
__device__ __forceinline__ uint32_t smem_u32(const void* p) {
    uint32_t a;
    asm("{ .reg .u64 t; cvta.to.shared.u64 t, %1; cvt.u32.u64 %0, t; }" : "=r"(a) : "l"(p));
    return a;
}
__device__ __forceinline__ void cpa16(uint32_t dst, const void* src) {
    asm volatile("cp.async.cg.shared.global [%0], [%1], 16;\n" :: "r"(dst), "l"(src));
}
__device__ __forceinline__ void cpa_commit() {
    asm volatile("cp.async.commit_group;\n" ::: "memory");
}
__device__ __forceinline__ void cpa_wait2() {
    asm volatile("cp.async.wait_group 2;\n" ::: "memory");
}
__device__ __forceinline__ void cpa_wait1() {
    asm volatile("cp.async.wait_group 1;\n" ::: "memory");
}
__device__ __forceinline__ void cpa_wait0() {
    asm volatile("cp.async.wait_group 0;\n" ::: "memory");
}
__device__ __forceinline__ void ldsm_x4(uint32_t& r0, uint32_t& r1, uint32_t& r2, uint32_t& r3,
                                        uint32_t addr) {
    asm volatile("ldmatrix.sync.aligned.m8n8.x4.shared.b16 {%0,%1,%2,%3}, [%4];"
                 : "=r"(r0), "=r"(r1), "=r"(r2), "=r"(r3) : "r"(addr));
}
__device__ __forceinline__ void mma16816(float& d0, float& d1, float& d2, float& d3,
                                         uint32_t a0, uint32_t a1, uint32_t a2, uint32_t a3,
                                         uint32_t b0, uint32_t b1) {
    asm volatile(
        "mma.sync.aligned.m16n8k16.row.col.f32.f16.f16.f32 "
        "{%0,%1,%2,%3}, {%4,%5,%6,%7}, {%8,%9}, {%0,%1,%2,%3};"
        : "+f"(d0), "+f"(d1), "+f"(d2), "+f"(d3)
        : "r"(a0), "r"(a1), "r"(a2), "r"(a3), "r"(b0), "r"(b1));
}

// ---------------------------------------------------------------------------
// K0: weights fp32 -> fp16
// ---------------------------------------------------------------------------
__global__ __launch_bounds__(256)
void conv_w_kernel(const float* __restrict__ Wk,
                   const float* __restrict__ Wv,
                   const float* __restrict__ Wr)
{
    int which = blockIdx.y;
    int i = blockIdx.x * 256 + threadIdx.x;
    const float* src = (which == 0) ? Wk : (which == 1) ? Wv : Wr;
    g_W16[which][i] = __float2half_rn(src[i]);
}

// ---------------------------------------------------------------------------
// K1: embedding gather + time-mix -> fp16 xk, xv, xr (8 channels per thread)
// ---------------------------------------------------------------------------
__global__ __launch_bounds__(256)
void embed_mix_kernel(const int*   __restrict__ tok,
                      const float* __restrict__ xx_init,
                      const float* __restrict__ emb,
                      const float* __restrict__ tmk,
                      const float* __restrict__ tmv,
                      const float* __restrict__ tmr)
{
    int idx8 = blockIdx.x * blockDim.x + threadIdx.x;   // < BTC/8
    int c8 = idx8 & 127;
    int bt = idx8 >> 7;
    int t  = bt & (T_ - 1);
    int b  = bt >> 11;
    int c  = c8 * 8;

    int token = tok[bt];
    const float* cur = &emb[(size_t)token * C_ + c];
    const float* prv = (t == 0) ? &xx_init[b * C_ + c]
                                : &emb[(size_t)tok[bt - 1] * C_ + c];

    float4 xc0 = *(const float4*)(cur);
    float4 xc1 = *(const float4*)(cur + 4);
    float4 xp0 = *(const float4*)(prv);
    float4 xp1 = *(const float4*)(prv + 4);

#define MIX8(arr, mixp)  do {                                               \
        float4 m0 = *(const float4*)&(mixp)[c];                             \
        float4 m1 = *(const float4*)&(mixp)[c + 4];                         \
        float v0 = xc0.x * m0.x + xp0.x * (1.0f - m0.x);                    \
        float v1 = xc0.y * m0.y + xp0.y * (1.0f - m0.y);                    \
        float v2 = xc0.z * m0.z + xp0.z * (1.0f - m0.z);                    \
        float v3 = xc0.w * m0.w + xp0.w * (1.0f - m0.w);                    \
        float v4 = xc1.x * m1.x + xp1.x * (1.0f - m1.x);                    \
        float v5 = xc1.y * m1.y + xp1.y * (1.0f - m1.y);                    \
        float v6 = xc1.z * m1.z + xp1.z * (1.0f - m1.z);                    \
        float v7 = xc1.w * m1.w + xp1.w * (1.0f - m1.w);                    \
        __half2 h01 = __halves2half2(__float2half_rn(v0), __float2half_rn(v1)); \
        __half2 h23 = __halves2half2(__float2half_rn(v2), __float2half_rn(v3)); \
        __half2 h45 = __halves2half2(__float2half_rn(v4), __float2half_rn(v5)); \
        __half2 h67 = __halves2half2(__float2half_rn(v6), __float2half_rn(v7)); \
        uint4 pack = make_uint4(*(uint32_t*)&h01, *(uint32_t*)&h23,         \
                                *(uint32_t*)&h45, *(uint32_t*)&h67);        \
        *reinterpret_cast<uint4*>(&(arr)[(size_t)idx8 * 8]) = pack;         \
    } while (0)

    MIX8(g_xk, tmk);
    MIX8(g_xv, tmv);
    MIX8(g_xr, tmr);
#undef MIX8
}

// ---------------------------------------------------------------------------
// K2: fp16 NT GEMM: C[M,N] = A[M,K] * W[N,K]^T  (fp32 accumulate, fp16 out).
// Tiles: 128x256x64 block (wider N cuts A L2-traffic 2x: per-which traffic
// 512MB -> 384MB), 8 warps, warp tile 64x64, 4-stage cp.async, occ=1.
// SMEM rows = 128B data + 16B pad (144B) => conflict-free ldmatrix.
// blockIdx.z: 0 -> k, 1 -> v, 2 -> sigmoid -> r
// ---------------------------------------------------------------------------
#define BM 128
#define BN 256
#define BK 64
#define ROWB 144                          // 128 data + 16 pad
#define AT_BYTES (BM * ROWB)              // 18432
#define BT_BYTES (BN * ROWB)              // 36864
#define STAGEB (AT_BYTES + BT_BYTES)      // 55296
#define NSTAGE 4
#define GEMM_SMEM (NSTAGE * STAGEB)       // 221184 (occ = 1)
#define NKT (C_ / BK)                     // 16 K-chunks

__global__ __launch_bounds__(256, 1)
void gemm_mma_kernel()
{
    extern __shared__ char smem[];
    const uint32_t sb = smem_u32(smem);
    const int tid  = threadIdx.x;
    const int wid  = tid >> 5;
    const int lane = tid & 31;

    const int which = blockIdx.z;
    const int n0 = blockIdx.x * BN;
    const int m0 = blockIdx.y * BM;

    const __half* Ap = (which == 0) ? g_xk : (which == 1) ? g_xv : g_xr;
    const __half* Wp = g_W16[which];
    __half* __restrict__ Cout = (which == 0) ? g_k16 : (which == 1) ? g_v16 : g_r16;

    const char* A_g = (const char*)(Ap + (size_t)m0 * C_);
    const char* W_g = (const char*)(Wp + (size_t)n0 * C_);

    const int warp_m = (wid & 1) * 64;   // 2 warps along M
    const int warp_n = (wid >> 1) * 64;  // 4 warps along N

    float acc[4][8][4];                  // 64x64 warp tile
#pragma unroll
    for (int i = 0; i < 4; i++)
#pragma unroll
        for (int j = 0; j < 8; j++)
#pragma unroll
            for (int q = 0; q < 4; q++) acc[i][j][q] = 0.0f;

    // Load one K-chunk: A (128 rows x 128B), W (256 rows x 128B)
    auto issue_stage = [&](int kt, int stg) {
        const int kb = kt * BK * 2;              // byte offset along K (128B)
        uint32_t base = sb + stg * STAGEB;
        for (int g = tid; g < 1024; g += 256) {  // A: 128 rows x 8 granules
            int r = g >> 3;
            int c = g & 7;
            cpa16(base + r * ROWB + c * 16, A_g + (size_t)r * (C_ * 2) + kb + c * 16);
        }
        for (int g = tid; g < 2048; g += 256) {  // W: 256 rows x 8 granules
            int r = g >> 3;
            int c = g & 7;
            cpa16(base + AT_BYTES + r * ROWB + c * 16,
                  W_g + (size_t)r * (C_ * 2) + kb + c * 16);
        }
        cpa_commit();
    };

    issue_stage(0, 0);
    issue_stage(1, 1);
    issue_stage(2, 2);

    const int l15 = lane & 15;
    const int l7  = lane & 7;
    const int b_rowadd = ((lane >> 4) & 1) * 8 + l7;
    const int b_koff   = ((lane >> 3) & 1) * 16;

    for (int kt = 0; kt < NKT; kt++) {
        if (kt < NKT - 2)       cpa_wait2();
        else if (kt == NKT - 2) cpa_wait1();
        else                    cpa_wait0();
        __syncthreads();
        if (kt + 3 < NKT) issue_stage(kt + 3, (kt + 3) % NSTAGE);

        const uint32_t base = sb + (kt % NSTAGE) * STAGEB;
        const uint32_t ah = base;
        const uint32_t bw = base + AT_BYTES;

#pragma unroll
        for (int ks = 0; ks < 4; ks++) {          // 4 x K16 within 64-chunk
            uint32_t af[4][4];
            uint32_t bf[8][2];
            const uint32_t arow = (warp_m + l15) * ROWB + ks * 32 + (lane >> 4) * 16;
#pragma unroll
            for (int mt = 0; mt < 4; mt++)
                ldsm_x4(af[mt][0], af[mt][1], af[mt][2], af[mt][3],
                        ah + arow + mt * (16 * ROWB));
#pragma unroll
            for (int p = 0; p < 4; p++) {
                uint32_t addr = bw + (warp_n + p * 16 + b_rowadd) * ROWB + ks * 32 + b_koff;
                ldsm_x4(bf[2*p][0], bf[2*p][1], bf[2*p+1][0], bf[2*p+1][1], addr);
            }
#pragma unroll
            for (int mt = 0; mt < 4; mt++)
#pragma unroll
                for (int nt = 0; nt < 8; nt++)
                    mma16816(acc[mt][nt][0], acc[mt][nt][1], acc[mt][nt][2], acc[mt][nt][3],
                             af[mt][0], af[mt][1], af[mt][2], af[mt][3],
                             bf[nt][0], bf[nt][1]);
        }
    }

    // ---- epilogue: fp16 half2 stores direct to global
    const int rbase = m0 + warp_m + (lane >> 2);
    const int cbase = n0 + warp_n + (lane & 3) * 2;
#pragma unroll
    for (int mt = 0; mt < 4; mt++) {
#pragma unroll
        for (int nt = 0; nt < 8; nt++) {
            float v0 = acc[mt][nt][0], v1 = acc[mt][nt][1];
            float v2 = acc[mt][nt][2], v3 = acc[mt][nt][3];
            if (which == 2) {
                v0 = 1.0f / (1.0f + __expf(-v0));
                v1 = 1.0f / (1.0f + __expf(-v1));
                v2 = 1.0f / (1.0f + __expf(-v2));
                v3 = 1.0f / (1.0f + __expf(-v3));
            }
            size_t r0 = (size_t)(rbase + mt * 16) * C_ + cbase + nt * 8;
            size_t r1 = r0 + 8 * C_;
            *reinterpret_cast<__half2*>(&Cout[r0]) =
                __halves2half2(__float2half_rn(v0), __float2half_rn(v1));
            *reinterpret_cast<__half2*>(&Cout[r1]) =
                __halves2half2(__float2half_rn(v2), __float2half_rn(v3));
        }
    }
}

// ---------------------------------------------------------------------------
// K3a: chunk-local WKV summaries. 2 channels/thread (ILP=2), half2 loads.
// ---------------------------------------------------------------------------
__global__ __launch_bounds__(256)
void wkv_passA(const float* __restrict__ time_decay)
{
    const int tid = blockIdx.x * blockDim.x + threadIdx.x;  // 0..131071
    const int bc2 = tid & (BC_/2 - 1);       // 0..4095
    const int j   = tid >> 12;               // 0..31
    const int bc  = bc2 * 2;
    const int c   = bc & (C_ - 1);
    const int b   = bc >> 10;

    const float w0 = -expf(time_decay[c]);
    const float w1 = -expf(time_decay[c + 1]);
    float aa0 = 0.0f, bb0 = 0.0f, pp0 = -1e30f;
    float aa1 = 0.0f, bb1 = 0.0f, pp1 = -1e30f;

    const int base = (b * T_ + j * CL) * C_ + c;
#pragma unroll 4
    for (int i = 0; i < CL; i++) {
        __half2 kh = *reinterpret_cast<const __half2*>(&g_k16[base + i * C_]);
        __half2 vh = *reinterpret_cast<const __half2*>(&g_v16[base + i * C_]);
        float2 kf = __half22float2(kh);
        float2 vf = __half22float2(vh);
        {
            float ww2 = pp0 + w0;
            float d2  = ww2 - kf.x;
            float es  = __expf(-fabsf(d2));
            float e1  = (d2 >= 0.0f) ? 1.0f : es;
            float e2  = (d2 >= 0.0f) ? es : 1.0f;
            aa0 = e1 * aa0 + e2 * vf.x;
            bb0 = e1 * bb0 + e2;
            pp0 = fmaxf(ww2, kf.x);
        }
        {
            float ww2 = pp1 + w1;
            float d2  = ww2 - kf.y;
            float es  = __expf(-fabsf(d2));
            float e1  = (d2 >= 0.0f) ? 1.0f : es;
            float e2  = (d2 >= 0.0f) ? es : 1.0f;
            aa1 = e1 * aa1 + e2 * vf.y;
            bb1 = e1 * bb1 + e2;
            pp1 = fmaxf(ww2, kf.y);
        }
    }
    g_chA[j][bc]     = aa0;  g_chA[j][bc + 1] = aa1;
    g_chB[j][bc]     = bb0;  g_chB[j][bc + 1] = bb1;
    g_chP[j][bc]     = pp0;  g_chP[j][bc + 1] = pp1;
}

// ---------------------------------------------------------------------------
// K3b: serial compose over 32 chunk summaries -> incoming state per chunk.
// ---------------------------------------------------------------------------
__global__ __launch_bounds__(256)
void wkv_passB(const float* __restrict__ aa_init,
               const float* __restrict__ bb_init,
               const float* __restrict__ pp_init,
               const float* __restrict__ time_decay)
{
    const int bc = blockIdx.x * blockDim.x + threadIdx.x;  // 0..8191
    const int c  = bc & (C_ - 1);

    float aa = aa_init[bc], bb = bb_init[bc], pp = pp_init[bc];
    const float Lw = (float)CL * (-expf(time_decay[c]));

#pragma unroll
    for (int j = 0; j < NCH; j++) {
        g_inA[j][bc] = aa;
        g_inB[j][bc] = bb;
        g_inP[j][bc] = pp;
        float q  = pp + Lw;
        float Pj = g_chP[j][bc];
        float Aj = g_chA[j][bc];
        float Bj = g_chB[j][bc];
        float Pn = fmaxf(q, Pj);
        float e1 = __expf(q - Pn);
        float e2 = __expf(Pj - Pn);
        aa = e1 * aa + e2 * Aj;
        bb = e1 * bb + e2 * Bj;
        pp = Pn;
    }
}

// ---------------------------------------------------------------------------
// K3c: replay each chunk with incoming state; 2 channels/thread, half2 loads.
// ---------------------------------------------------------------------------
__global__ __launch_bounds__(256)
void wkv_passC(const float* __restrict__ time_decay,
               const float* __restrict__ time_first)
{
    const int tid = blockIdx.x * blockDim.x + threadIdx.x;  // 0..131071
    const int bc2 = tid & (BC_/2 - 1);
    const int j   = tid >> 12;
    const int bc  = bc2 * 2;
    const int c   = bc & (C_ - 1);
    const int b   = bc >> 10;

    const float w0 = -expf(time_decay[c]);
    const float w1 = -expf(time_decay[c + 1]);
    const float u0 = time_first[c];
    const float u1 = time_first[c + 1];

    float aa0 = g_inA[j][bc],     bb0 = g_inB[j][bc],     pp0 = g_inP[j][bc];
    float aa1 = g_inA[j][bc + 1], bb1 = g_inB[j][bc + 1], pp1 = g_inP[j][bc + 1];

    float ysum0 = 0.0f, ysum1 = 0.0f;
    float y0 = 0.0f, y1 = 0.0f;

    const int base = (b * T_ + j * CL) * C_ + c;
#pragma unroll 4
    for (int i = 0; i < CL; i++) {
        __half2 kh = *reinterpret_cast<const __half2*>(&g_k16[base + i * C_]);
        __half2 vh = *reinterpret_cast<const __half2*>(&g_v16[base + i * C_]);
        __half2 rh = *reinterpret_cast<const __half2*>(&g_r16[base + i * C_]);
        float2 kf = __half22float2(kh);
        float2 vf = __half22float2(vh);
        float2 rf = __half22float2(rh);
        {
            float ww = u0 + kf.x;
            float d  = pp0 - ww;
            float es = __expf(-fabsf(d));
            float e1 = (d >= 0.0f) ? 1.0f : es;
            float e2 = (d >= 0.0f) ? es : 1.0f;
            y0 = rf.x * __fdividef(e1 * aa0 + e2 * vf.x, e1 * bb0 + e2);
            ysum0 += y0;
            float ww2 = pp0 + w0;
            float d2  = ww2 - kf.x;
            float es2 = __expf(-fabsf(d2));
            float e1b = (d2 >= 0.0f) ? 1.0f : es2;
            float e2b = (d2 >= 0.0f) ? es2 : 1.0f;
            aa0 = e1b * aa0 + e2b * vf.x;
            bb0 = e1b * bb0 + e2b;
            pp0 = fmaxf(ww2, kf.x);
        }
        {
            float ww = u1 + kf.y;
            float d  = pp1 - ww;
            float es = __expf(-fabsf(d));
            float e1 = (d >= 0.0f) ? 1.0f : es;
            float e2 = (d >= 0.0f) ? es : 1.0f;
            y1 = rf.y * __fdividef(e1 * aa1 + e2 * vf.y, e1 * bb1 + e2);
            ysum1 += y1;
            float ww2 = pp1 + w1;
            float d2  = ww2 - kf.y;
            float es2 = __expf(-fabsf(d2));
            float e1b = (d2 >= 0.0f) ? 1.0f : es2;
            float e2b = (d2 >= 0.0f) ? es2 : 1.0f;
            aa1 = e1b * aa1 + e2b * vf.y;
            bb1 = e1b * bb1 + e2b;
            pp1 = fmaxf(ww2, kf.y);
        }
    }
    g_psum[j][bc]     = ysum0;
    g_psum[j][bc + 1] = ysum1;
    if (j == NCH - 1) {
        g_ylast[bc]     = y0;
        g_ylast[bc + 1] = y1;
    }
}

// ---------------------------------------------------------------------------
// K3d: reduce partials -> z = 0.5*(ylast + mean)
// ---------------------------------------------------------------------------
__global__ __launch_bounds__(256)
void wkv_reduce()
{
    const int bc = blockIdx.x * blockDim.x + threadIdx.x;  // 0..8191
    float s = 0.0f;
#pragma unroll
    for (int j = 0; j < NCH; j++) s += g_psum[j][bc];
    g_z[bc] = 0.5f * (g_ylast[bc] + s * (1.0f / (float)T_));
}

// ---------------------------------------------------------------------------
// K4: tiny output GEMM hx[b,d] = sum_c z[b,c] * Wo[d,c]; out = stack([hx,hx])
// ---------------------------------------------------------------------------
__global__ __launch_bounds__(256)
void final_proj_kernel(const float* __restrict__ Wo,
                       float* __restrict__ out)
{
    int gw   = (blockIdx.x * blockDim.x + threadIdx.x) >> 5;
    int lane = threadIdx.x & 31;
    if (gw >= BC_) return;
    int b = gw >> 10;
    int d = gw & (C_ - 1);

    const float* z  = g_z + b * C_;
    const float* wr = Wo + (size_t)d * C_;
    float s = 0.0f;
#pragma unroll 8
    for (int c = lane; c < C_; c += 32)
        s = fmaf(z[c], wr[c], s);
#pragma unroll
    for (int o = 16; o > 0; o >>= 1)
        s += __shfl_xor_sync(0xFFFFFFFFu, s, o);
    if (lane == 0) {
        out[b * C_ + d]       = s;
        out[BC_ + b * C_ + d] = s;
    }
}

// ---------------------------------------------------------------------------
extern "C" void kernel_launch(void* const* d_in, const int* in_sizes, int n_in,
                              void* d_out, int out_size)
{
    const int*   tok  = (const int*)  d_in[0];
    const float* xx   = (const float*)d_in[1];
    const float* aa   = (const float*)d_in[2];
    const float* bb   = (const float*)d_in[3];
    const float* pp   = (const float*)d_in[4];
    const float* emb  = (const float*)d_in[5];
    const float* tmk  = (const float*)d_in[6];
    const float* tmv  = (const float*)d_in[7];
    const float* tmr  = (const float*)d_in[8];
    const float* tdec = (const float*)d_in[9];
    const float* tfir = (const float*)d_in[10];
    const float* Wk   = (const float*)d_in[11];
    const float* Wv   = (const float*)d_in[12];
    const float* Wr   = (const float*)d_in[13];
    const float* Wo   = (const float*)d_in[14];
    float* out = (float*)d_out;

    cudaFuncSetAttribute(gemm_mma_kernel,
                         cudaFuncAttributeMaxDynamicSharedMemorySize, GEMM_SMEM);

    dim3 wgrid(C_ * C_ / 256, 3);
    conv_w_kernel<<<wgrid, 256>>>(Wk, Wv, Wr);

    embed_mix_kernel<<<BTC / 8 / 256, 256>>>(tok, xx, emb, tmk, tmv, tmr);

    dim3 ggrid(C_ / BN, M_ / BM, 3);   // (4, 128, 3); x-fastest => A reuse in L2
    gemm_mma_kernel<<<ggrid, 256, GEMM_SMEM>>>();

    wkv_passA<<<(NCH * BC_ / 2) / 256, 256>>>(tdec);
    wkv_passB<<<BC_ / 256, 256>>>(aa, bb, pp, tdec);
    wkv_passC<<<(NCH * BC_ / 2) / 256, 256>>>(tdec, tfir);
    wkv_reduce<<<BC_ / 256, 256>>>();

    final_proj_kernel<<<(BC_ * 32) / 256, 256>>>(Wo, out);
}

// round 16
// speedup vs baseline: 1.7619x; 1.7619x over previous
#include <cuda_runtime.h>
#include <cuda_fp16.h>
#include <cstdint>
#include <cmath>

// Problem constants
#define B_   8
#define T_   2048
#define C_   1024
#define M_   (B_*T_)       // 16384
#define BTC  (B_*T_*C_)    // 16777216
#define BC_  (B_*C_)       // 8192

// Chunked scan
#define NCH 32
#define CL  (T_/NCH)       // 64

// ---------------------------------------------------------------------------
// Scratch (__device__ globals; no cudaMalloc allowed)
// ---------------------------------------------------------------------------
__device__ __half g_xk[BTC];
__device__ __half g_xv[BTC];
__device__ __half g_xr[BTC];
__device__ __half g_W16[3][C_*C_];
__device__ __half g_k16[BTC], g_v16[BTC], g_r16[BTC];
// scan scratch
__device__ float g_chA[NCH][BC_], g_chB[NCH][BC_], g_chP[NCH][BC_];
__device__ float g_inA[NCH][BC_], g_inB[NCH][BC_], g_inP[NCH][BC_];
__device__ float g_psum[NCH][BC_];
__device__ float g_ylast[BC_];
__device__ float g_z[BC_];

// ---------------------------------------------------------------------------
// Generic-PTX helpers (sm_80-class; safe for the harness's compute_103 build)
// ---------------------------------------------------------------------------
__device__ __forceinline__ uint32_t smem_u32(const void* p) {
    uint32_t a;
    asm("{ .reg .u64 t; cvta.to.shared.u64 t, %1; cvt.u32.u64 %0, t; }" : "=r"(a) : "l"(p));
    return a;
}
__device__ __forceinline__ void cpa16(uint32_t dst, const void* src) {
    asm volatile("cp.async.cg.shared.global [%0], [%1], 16;\n" :: "r"(dst), "l"(src));
}
__device__ __forceinline__ void cpa_commit() {
    asm volatile("cp.async.commit_group;\n" ::: "memory");
}
__device__ __forceinline__ void cpa_wait1() {
    asm volatile("cp.async.wait_group 1;\n" ::: "memory");
}
__device__ __forceinline__ void cpa_wait0() {
    asm volatile("cp.async.wait_group 0;\n" ::: "memory");
}
__device__ __forceinline__ void ldsm_x4(uint32_t& r0, uint32_t& r1, uint32_t& r2, uint32_t& r3,
                                        uint32_t addr) {
    asm volatile("ldmatrix.sync.aligned.m8n8.x4.shared.b16 {%0,%1,%2,%3}, [%4];"
                 : "=r"(r0), "=r"(r1), "=r"(r2), "=r"(r3) : "r"(addr));
}
__device__ __forceinline__ void mma16816(float& d0, float& d1, float& d2, float& d3,
                                         uint32_t a0, uint32_t a1, uint32_t a2, uint32_t a3,
                                         uint32_t b0, uint32_t b1) {
    asm volatile(
        "mma.sync.aligned.m16n8k16.row.col.f32.f16.f16.f32 "
        "{%0,%1,%2,%3}, {%4,%5,%6,%7}, {%8,%9}, {%0,%1,%2,%3};"
        : "+f"(d0), "+f"(d1), "+f"(d2), "+f"(d3)
        : "r"(a0), "r"(a1), "r"(a2), "r"(a3), "r"(b0), "r"(b1));
}

// ---------------------------------------------------------------------------
// K1: fused prep — blockIdx.y = 0: embedding gather + time-mix (8 ch/thread)
//                  blockIdx.y = 1: weight fp32 -> fp16 conversion (x3)
// Independent workloads fused into one launch to cut graph nodes / tails.
// ---------------------------------------------------------------------------
__global__ __launch_bounds__(256)
void prep_kernel(const int*   __restrict__ tok,
                 const float* __restrict__ xx_init,
                 const float* __restrict__ emb,
                 const float* __restrict__ tmk,
                 const float* __restrict__ tmv,
                 const float* __restrict__ tmr,
                 const float* __restrict__ Wk,
                 const float* __restrict__ Wv,
                 const float* __restrict__ Wr)
{
    if (blockIdx.y == 1) {
        // weight conversion: 3 * C*C elements, 4 per thread
        int i4 = blockIdx.x * 256 + threadIdx.x;      // < 3*C*C/4 = 786432 -> grid.x 3072
        int which = i4 / (C_ * C_ / 4);
        int i = (i4 - which * (C_ * C_ / 4)) * 4;
        const float* src = (which == 0) ? Wk : (which == 1) ? Wv : Wr;
        float4 v = *(const float4*)&src[i];
        __half2 h01 = __halves2half2(__float2half_rn(v.x), __float2half_rn(v.y));
        __half2 h23 = __halves2half2(__float2half_rn(v.z), __float2half_rn(v.w));
        *reinterpret_cast<uint2*>(&g_W16[which][i]) =
            make_uint2(*(uint32_t*)&h01, *(uint32_t*)&h23);
        return;
    }

    int idx8 = blockIdx.x * blockDim.x + threadIdx.x;   // < BTC/8
    int c8 = idx8 & 127;
    int bt = idx8 >> 7;
    int t  = bt & (T_ - 1);
    int b  = bt >> 11;
    int c  = c8 * 8;

    int token = tok[bt];
    const float* cur = &emb[(size_t)token * C_ + c];
    const float* prv = (t == 0) ? &xx_init[b * C_ + c]
                                : &emb[(size_t)tok[bt - 1] * C_ + c];

    float4 xc0 = *(const float4*)(cur);
    float4 xc1 = *(const float4*)(cur + 4);
    float4 xp0 = *(const float4*)(prv);
    float4 xp1 = *(const float4*)(prv + 4);

#define MIX8(arr, mixp)  do {                                               \
        float4 m0 = *(const float4*)&(mixp)[c];                             \
        float4 m1 = *(const float4*)&(mixp)[c + 4];                         \
        float v0 = xc0.x * m0.x + xp0.x * (1.0f - m0.x);                    \
        float v1 = xc0.y * m0.y + xp0.y * (1.0f - m0.y);                    \
        float v2 = xc0.z * m0.z + xp0.z * (1.0f - m0.z);                    \
        float v3 = xc0.w * m0.w + xp0.w * (1.0f - m0.w);                    \
        float v4 = xc1.x * m1.x + xp1.x * (1.0f - m1.x);                    \
        float v5 = xc1.y * m1.y + xp1.y * (1.0f - m1.y);                    \
        float v6 = xc1.z * m1.z + xp1.z * (1.0f - m1.z);                    \
        float v7 = xc1.w * m1.w + xp1.w * (1.0f - m1.w);                    \
        __half2 h01 = __halves2half2(__float2half_rn(v0), __float2half_rn(v1)); \
        __half2 h23 = __halves2half2(__float2half_rn(v2), __float2half_rn(v3)); \
        __half2 h45 = __halves2half2(__float2half_rn(v4), __float2half_rn(v5)); \
        __half2 h67 = __halves2half2(__float2half_rn(v6), __float2half_rn(v7)); \
        uint4 pack = make_uint4(*(uint32_t*)&h01, *(uint32_t*)&h23,         \
                                *(uint32_t*)&h45, *(uint32_t*)&h67);        \
        *reinterpret_cast<uint4*>(&(arr)[(size_t)idx8 * 8]) = pack;         \
    } while (0)

    MIX8(g_xk, tmk);
    MIX8(g_xv, tmv);
    MIX8(g_xr, tmr);
#undef MIX8
}

// ---------------------------------------------------------------------------
// K2: fp16 NT GEMM: C[M,N] = A[M,K] * W[N,K]^T  (fp32 accumulate, fp16 out).
// R14 config (best measured): 128x128x64 block, 4 warps (128 thr), warp tile
// 64x64, 3-stage cp.async, 2 CTAs/SM.
// SMEM rows = 128B data + 16B pad (144B) => conflict-free ldmatrix.
// blockIdx.z: 0 -> k, 1 -> v, 2 -> sigmoid -> r
// ---------------------------------------------------------------------------
#define BM 128
#define BN 128
#define BK 64
#define ROWB 144                          // 128 data + 16 pad
#define AT_BYTES (BM * ROWB)              // 18432
#define BT_BYTES (BN * ROWB)              // 18432
#define STAGEB (AT_BYTES + BT_BYTES)      // 36864
#define NSTAGE 3
#define GEMM_SMEM (NSTAGE * STAGEB)       // 110592 (x2 CTAs = 221184)
#define NKT (C_ / BK)                     // 16 K-chunks
#define GTHREADS 128

__global__ __launch_bounds__(GTHREADS, 2)
void gemm_mma_kernel()
{
    extern __shared__ char smem[];
    const uint32_t sb = smem_u32(smem);
    const int tid  = threadIdx.x;
    const int wid  = tid >> 5;          // 0..3
    const int lane = tid & 31;

    const int which = blockIdx.z;
    const int n0 = blockIdx.x * BN;
    const int m0 = blockIdx.y * BM;

    const __half* Ap = (which == 0) ? g_xk : (which == 1) ? g_xv : g_xr;
    const __half* Wp = g_W16[which];
    __half* __restrict__ Cout = (which == 0) ? g_k16 : (which == 1) ? g_v16 : g_r16;

    const char* A_g = (const char*)(Ap + (size_t)m0 * C_);
    const char* W_g = (const char*)(Wp + (size_t)n0 * C_);

    const int warp_m = (wid & 1) * 64;   // 2 warps along M
    const int warp_n = (wid >> 1) * 64;  // 2 warps along N

    float acc[4][8][4];                  // 64x64 warp tile: 128 regs
#pragma unroll
    for (int i = 0; i < 4; i++)
#pragma unroll
        for (int j = 0; j < 8; j++)
#pragma unroll
            for (int q = 0; q < 4; q++) acc[i][j][q] = 0.0f;

    // Load one K-chunk: A (128 rows x 128B), W (128 rows x 128B)
    auto issue_stage = [&](int kt, int stg) {
        const int kb = kt * BK * 2;              // byte offset along K (128B)
        uint32_t base = sb + stg * STAGEB;
        for (int g = tid; g < 1024; g += GTHREADS) {  // A: 128 rows x 8 granules
            int r = g >> 3;
            int c = g & 7;
            cpa16(base + r * ROWB + c * 16, A_g + (size_t)r * (C_ * 2) + kb + c * 16);
        }
        for (int g = tid; g < 1024; g += GTHREADS) {  // W: 128 rows x 8 granules
            int r = g >> 3;
            int c = g & 7;
            cpa16(base + AT_BYTES + r * ROWB + c * 16,
                  W_g + (size_t)r * (C_ * 2) + kb + c * 16);
        }
        cpa_commit();
    };

    issue_stage(0, 0);
    issue_stage(1, 1);

    const int l15 = lane & 15;
    const int l7  = lane & 7;
    const int b_rowadd = ((lane >> 4) & 1) * 8 + l7;
    const int b_koff   = ((lane >> 3) & 1) * 16;

    for (int kt = 0; kt < NKT; kt++) {
        if (kt == NKT - 1) cpa_wait0(); else cpa_wait1();
        __syncthreads();
        if (kt + 2 < NKT) issue_stage(kt + 2, (kt + 2) % NSTAGE);

        const uint32_t base = sb + (kt % NSTAGE) * STAGEB;
        const uint32_t ah = base;
        const uint32_t bw = base + AT_BYTES;

#pragma unroll
        for (int ks = 0; ks < 4; ks++) {          // 4 x K16 within 64-chunk
            uint32_t af[4][4];
            uint32_t bf[8][2];
            const uint32_t arow = (warp_m + l15) * ROWB + ks * 32 + (lane >> 4) * 16;
#pragma unroll
            for (int mt = 0; mt < 4; mt++)
                ldsm_x4(af[mt][0], af[mt][1], af[mt][2], af[mt][3],
                        ah + arow + mt * (16 * ROWB));
#pragma unroll
            for (int p = 0; p < 4; p++) {
                uint32_t addr = bw + (warp_n + p * 16 + b_rowadd) * ROWB + ks * 32 + b_koff;
                ldsm_x4(bf[2*p][0], bf[2*p][1], bf[2*p+1][0], bf[2*p+1][1], addr);
            }
#pragma unroll
            for (int mt = 0; mt < 4; mt++)
#pragma unroll
                for (int nt = 0; nt < 8; nt++)
                    mma16816(acc[mt][nt][0], acc[mt][nt][1], acc[mt][nt][2], acc[mt][nt][3],
                             af[mt][0], af[mt][1], af[mt][2], af[mt][3],
                             bf[nt][0], bf[nt][1]);
        }
    }

    // ---- epilogue: fp16 half2 stores direct to global
    const int rbase = m0 + warp_m + (lane >> 2);
    const int cbase = n0 + warp_n + (lane & 3) * 2;
#pragma unroll
    for (int mt = 0; mt < 4; mt++) {
#pragma unroll
        for (int nt = 0; nt < 8; nt++) {
            float v0 = acc[mt][nt][0], v1 = acc[mt][nt][1];
            float v2 = acc[mt][nt][2], v3 = acc[mt][nt][3];
            if (which == 2) {
                v0 = 1.0f / (1.0f + __expf(-v0));
                v1 = 1.0f / (1.0f + __expf(-v1));
                v2 = 1.0f / (1.0f + __expf(-v2));
                v3 = 1.0f / (1.0f + __expf(-v3));
            }
            size_t r0 = (size_t)(rbase + mt * 16) * C_ + cbase + nt * 8;
            size_t r1 = r0 + 8 * C_;
            *reinterpret_cast<__half2*>(&Cout[r0]) =
                __halves2half2(__float2half_rn(v0), __float2half_rn(v1));
            *reinterpret_cast<__half2*>(&Cout[r1]) =
                __halves2half2(__float2half_rn(v2), __float2half_rn(v3));
        }
    }
}

// ---------------------------------------------------------------------------
// K3a: chunk-local WKV summaries. 2 channels/thread (ILP=2), half2 loads.
// ---------------------------------------------------------------------------
__global__ __launch_bounds__(256)
void wkv_passA(const float* __restrict__ time_decay)
{
    const int tid = blockIdx.x * blockDim.x + threadIdx.x;  // 0..131071
    const int bc2 = tid & (BC_/2 - 1);       // 0..4095
    const int j   = tid >> 12;               // 0..31
    const int bc  = bc2 * 2;
    const int c   = bc & (C_ - 1);
    const int b   = bc >> 10;

    const float w0 = -expf(time_decay[c]);
    const float w1 = -expf(time_decay[c + 1]);
    float aa0 = 0.0f, bb0 = 0.0f, pp0 = -1e30f;
    float aa1 = 0.0f, bb1 = 0.0f, pp1 = -1e30f;

    const int base = (b * T_ + j * CL) * C_ + c;
#pragma unroll 4
    for (int i = 0; i < CL; i++) {
        __half2 kh = *reinterpret_cast<const __half2*>(&g_k16[base + i * C_]);
        __half2 vh = *reinterpret_cast<const __half2*>(&g_v16[base + i * C_]);
        float2 kf = __half22float2(kh);
        float2 vf = __half22float2(vh);
        {
            float ww2 = pp0 + w0;
            float d2  = ww2 - kf.x;
            float es  = __expf(-fabsf(d2));
            float e1  = (d2 >= 0.0f) ? 1.0f : es;
            float e2  = (d2 >= 0.0f) ? es : 1.0f;
            aa0 = e1 * aa0 + e2 * vf.x;
            bb0 = e1 * bb0 + e2;
            pp0 = fmaxf(ww2, kf.x);
        }
        {
            float ww2 = pp1 + w1;
            float d2  = ww2 - kf.y;
            float es  = __expf(-fabsf(d2));
            float e1  = (d2 >= 0.0f) ? 1.0f : es;
            float e2  = (d2 >= 0.0f) ? es : 1.0f;
            aa1 = e1 * aa1 + e2 * vf.y;
            bb1 = e1 * bb1 + e2;
            pp1 = fmaxf(ww2, kf.y);
        }
    }
    g_chA[j][bc]     = aa0;  g_chA[j][bc + 1] = aa1;
    g_chB[j][bc]     = bb0;  g_chB[j][bc + 1] = bb1;
    g_chP[j][bc]     = pp0;  g_chP[j][bc + 1] = pp1;
}

// ---------------------------------------------------------------------------
// K3b: serial compose over 32 chunk summaries -> incoming state per chunk.
// ---------------------------------------------------------------------------
__global__ __launch_bounds__(256)
void wkv_passB(const float* __restrict__ aa_init,
               const float* __restrict__ bb_init,
               const float* __restrict__ pp_init,
               const float* __restrict__ time_decay)
{
    const int bc = blockIdx.x * blockDim.x + threadIdx.x;  // 0..8191
    const int c  = bc & (C_ - 1);

    float aa = aa_init[bc], bb = bb_init[bc], pp = pp_init[bc];
    const float Lw = (float)CL * (-expf(time_decay[c]));

#pragma unroll
    for (int j = 0; j < NCH; j++) {
        g_inA[j][bc] = aa;
        g_inB[j][bc] = bb;
        g_inP[j][bc] = pp;
        float q  = pp + Lw;
        float Pj = g_chP[j][bc];
        float Aj = g_chA[j][bc];
        float Bj = g_chB[j][bc];
        float Pn = fmaxf(q, Pj);
        float e1 = __expf(q - Pn);
        float e2 = __expf(Pj - Pn);
        aa = e1 * aa + e2 * Aj;
        bb = e1 * bb + e2 * Bj;
        pp = Pn;
    }
}

// ---------------------------------------------------------------------------
// K3c: replay each chunk with incoming state; 2 channels/thread, half2 loads.
// ---------------------------------------------------------------------------
__global__ __launch_bounds__(256)
void wkv_passC(const float* __restrict__ time_decay,
               const float* __restrict__ time_first)
{
    const int tid = blockIdx.x * blockDim.x + threadIdx.x;  // 0..131071
    const int bc2 = tid & (BC_/2 - 1);
    const int j   = tid >> 12;
    const int bc  = bc2 * 2;
    const int c   = bc & (C_ - 1);
    const int b   = bc >> 10;

    const float w0 = -expf(time_decay[c]);
    const float w1 = -expf(time_decay[c + 1]);
    const float u0 = time_first[c];
    const float u1 = time_first[c + 1];

    float aa0 = g_inA[j][bc],     bb0 = g_inB[j][bc],     pp0 = g_inP[j][bc];
    float aa1 = g_inA[j][bc + 1], bb1 = g_inB[j][bc + 1], pp1 = g_inP[j][bc + 1];

    float ysum0 = 0.0f, ysum1 = 0.0f;
    float y0 = 0.0f, y1 = 0.0f;

    const int base = (b * T_ + j * CL) * C_ + c;
#pragma unroll 4
    for (int i = 0; i < CL; i++) {
        __half2 kh = *reinterpret_cast<const __half2*>(&g_k16[base + i * C_]);
        __half2 vh = *reinterpret_cast<const __half2*>(&g_v16[base + i * C_]);
        __half2 rh = *reinterpret_cast<const __half2*>(&g_r16[base + i * C_]);
        float2 kf = __half22float2(kh);
        float2 vf = __half22float2(vh);
        float2 rf = __half22float2(rh);
        {
            float ww = u0 + kf.x;
            float d  = pp0 - ww;
            float es = __expf(-fabsf(d));
            float e1 = (d >= 0.0f) ? 1.0f : es;
            float e2 = (d >= 0.0f) ? es : 1.0f;
            y0 = rf.x * __fdividef(e1 * aa0 + e2 * vf.x, e1 * bb0 + e2);
            ysum0 += y0;
            float ww2 = pp0 + w0;
            float d2  = ww2 - kf.x;
            float es2 = __expf(-fabsf(d2));
            float e1b = (d2 >= 0.0f) ? 1.0f : es2;
            float e2b = (d2 >= 0.0f) ? es2 : 1.0f;
            aa0 = e1b * aa0 + e2b * vf.x;
            bb0 = e1b * bb0 + e2b;
            pp0 = fmaxf(ww2, kf.x);
        }
        {
            float ww = u1 + kf.y;
            float d  = pp1 - ww;
            float es = __expf(-fabsf(d));
            float e1 = (d >= 0.0f) ? 1.0f : es;
            float e2 = (d >= 0.0f) ? es : 1.0f;
            y1 = rf.y * __fdividef(e1 * aa1 + e2 * vf.y, e1 * bb1 + e2);
            ysum1 += y1;
            float ww2 = pp1 + w1;
            float d2  = ww2 - kf.y;
            float es2 = __expf(-fabsf(d2));
            float e1b = (d2 >= 0.0f) ? 1.0f : es2;
            float e2b = (d2 >= 0.0f) ? es2 : 1.0f;
            aa1 = e1b * aa1 + e2b * vf.y;
            bb1 = e1b * bb1 + e2b;
            pp1 = fmaxf(ww2, kf.y);
        }
    }
    g_psum[j][bc]     = ysum0;
    g_psum[j][bc + 1] = ysum1;
    if (j == NCH - 1) {
        g_ylast[bc]     = y0;
        g_ylast[bc + 1] = y1;
    }
}

// ---------------------------------------------------------------------------
// K3d: reduce partials -> z = 0.5*(ylast + mean)
// ---------------------------------------------------------------------------
__global__ __launch_bounds__(256)
void wkv_reduce()
{
    const int bc = blockIdx.x * blockDim.x + threadIdx.x;  // 0..8191
    float s = 0.0f;
#pragma unroll
    for (int j = 0; j < NCH; j++) s += g_psum[j][bc];
    g_z[bc] = 0.5f * (g_ylast[bc] + s * (1.0f / (float)T_));
}

// ---------------------------------------------------------------------------
// K4: tiny output GEMM hx[b,d] = sum_c z[b,c] * Wo[d,c]; out = stack([hx,hx])
// ---------------------------------------------------------------------------
__global__ __launch_bounds__(256)
void final_proj_kernel(const float* __restrict__ Wo,
                       float* __restrict__ out)
{
    int gw   = (blockIdx.x * blockDim.x + threadIdx.x) >> 5;
    int lane = threadIdx.x & 31;
    if (gw >= BC_) return;
    int b = gw >> 10;
    int d = gw & (C_ - 1);

    const float* z  = g_z + b * C_;
    const float* wr = Wo + (size_t)d * C_;
    float s = 0.0f;
#pragma unroll 8
    for (int c = lane; c < C_; c += 32)
        s = fmaf(z[c], wr[c], s);
#pragma unroll
    for (int o = 16; o > 0; o >>= 1)
        s += __shfl_xor_sync(0xFFFFFFFFu, s, o);
    if (lane == 0) {
        out[b * C_ + d]       = s;
        out[BC_ + b * C_ + d] = s;
    }
}

// ---------------------------------------------------------------------------
extern "C" void kernel_launch(void* const* d_in, const int* in_sizes, int n_in,
                              void* d_out, int out_size)
{
    const int*   tok  = (const int*)  d_in[0];
    const float* xx   = (const float*)d_in[1];
    const float* aa   = (const float*)d_in[2];
    const float* bb   = (const float*)d_in[3];
    const float* pp   = (const float*)d_in[4];
    const float* emb  = (const float*)d_in[5];
    const float* tmk  = (const float*)d_in[6];
    const float* tmv  = (const float*)d_in[7];
    const float* tmr  = (const float*)d_in[8];
    const float* tdec = (const float*)d_in[9];
    const float* tfir = (const float*)d_in[10];
    const float* Wk   = (const float*)d_in[11];
    const float* Wv   = (const float*)d_in[12];
    const float* Wr   = (const float*)d_in[13];
    const float* Wo   = (const float*)d_in[14];
    float* out = (float*)d_out;

    cudaFuncSetAttribute(gemm_mma_kernel,
                         cudaFuncAttributeMaxDynamicSharedMemorySize, GEMM_SMEM);

    // Fused prep: y=0 -> embed+mix (8192 blocks), y=1 -> weight conv (3072 blocks)
    dim3 pgrid(BTC / 8 / 256, 2);
    prep_kernel<<<pgrid, 256>>>(tok, xx, emb, tmk, tmv, tmr, Wk, Wv, Wr);

    dim3 ggrid(C_ / BN, M_ / BM, 3);   // (8, 128, 3)
    gemm_mma_kernel<<<ggrid, GTHREADS, GEMM_SMEM>>>();

    wkv_passA<<<(NCH * BC_ / 2) / 256, 256>>>(tdec);
    wkv_passB<<<BC_ / 256, 256>>>(aa, bb, pp, tdec);
    wkv_passC<<<(NCH * BC_ / 2) / 256, 256>>>(tdec, tfir);
    wkv_reduce<<<BC_ / 256, 256>>>();

    final_proj_kernel<<<(BC_ * 32) / 256, 256>>>(Wo, out);
}

// round 17
// speedup vs baseline: 1.7940x; 1.0182x over previous
#include <cuda_runtime.h>
#include <cuda_fp16.h>
#include <cstdint>
#include <cmath>

// Problem constants
#define B_   8
#define T_   2048
#define C_   1024
#define M_   (B_*T_)       // 16384
#define BTC  (B_*T_*C_)    // 16777216
#define BC_  (B_*C_)       // 8192

// Chunked scan
#define NCH 32
#define CL  (T_/NCH)       // 64

// ---------------------------------------------------------------------------
// Scratch (__device__ globals; no cudaMalloc allowed)
// ---------------------------------------------------------------------------
__device__ __half g_xk[BTC];
__device__ __half g_xv[BTC];
__device__ __half g_xr[BTC];
__device__ __half g_W16[3][C_*C_];
__device__ __half g_k16[BTC], g_v16[BTC], g_r16[BTC];
// scan scratch
__device__ float g_chA[NCH][BC_], g_chB[NCH][BC_], g_chP[NCH][BC_];
__device__ float g_inA[NCH][BC_], g_inB[NCH][BC_], g_inP[NCH][BC_];
__device__ float g_psum[NCH][BC_];
__device__ float g_ylast[BC_];
__device__ float g_z[BC_];

// ---------------------------------------------------------------------------
// Generic-PTX helpers (sm_80-class; safe for the harness's compute_103 build)
// ---------------------------------------------------------------------------
__device__ __forceinline__ uint32_t smem_u32(const void* p) {
    uint32_t a;
    asm("{ .reg .u64 t; cvta.to.shared.u64 t, %1; cvt.u32.u64 %0, t; }" : "=r"(a) : "l"(p));
    return a;
}
__device__ __forceinline__ void cpa16(uint32_t dst, const void* src) {
    asm volatile("cp.async.cg.shared.global [%0], [%1], 16;\n" :: "r"(dst), "l"(src));
}
__device__ __forceinline__ void cpa_commit() {
    asm volatile("cp.async.commit_group;\n" ::: "memory");
}
__device__ __forceinline__ void cpa_wait1() {
    asm volatile("cp.async.wait_group 1;\n" ::: "memory");
}
__device__ __forceinline__ void cpa_wait0() {
    asm volatile("cp.async.wait_group 0;\n" ::: "memory");
}
__device__ __forceinline__ void ldsm_x4(uint32_t& r0, uint32_t& r1, uint32_t& r2, uint32_t& r3,
                                        uint32_t addr) {
    asm volatile("ldmatrix.sync.aligned.m8n8.x4.shared.b16 {%0,%1,%2,%3}, [%4];"
                 : "=r"(r0), "=r"(r1), "=r"(r2), "=r"(r3) : "r"(addr));
}
__device__ __forceinline__ void mma16816(float& d0, float& d1, float& d2, float& d3,
                                         uint32_t a0, uint32_t a1, uint32_t a2, uint32_t a3,
                                         uint32_t b0, uint32_t b1) {
    asm volatile(
        "mma.sync.aligned.m16n8k16.row.col.f32.f16.f16.f32 "
        "{%0,%1,%2,%3}, {%4,%5,%6,%7}, {%8,%9}, {%0,%1,%2,%3};"
        : "+f"(d0), "+f"(d1), "+f"(d2), "+f"(d3)
        : "r"(a0), "r"(a1), "r"(a2), "r"(a3), "r"(b0), "r"(b1));
}

// ---------------------------------------------------------------------------
// K1: fused prep — blockIdx.y = 0: embedding gather + time-mix (8 ch/thread)
//                  blockIdx.y = 1: weight fp32 -> fp16 conversion (x3)
// ---------------------------------------------------------------------------
__global__ __launch_bounds__(256)
void prep_kernel(const int*   __restrict__ tok,
                 const float* __restrict__ xx_init,
                 const float* __restrict__ emb,
                 const float* __restrict__ tmk,
                 const float* __restrict__ tmv,
                 const float* __restrict__ tmr,
                 const float* __restrict__ Wk,
                 const float* __restrict__ Wv,
                 const float* __restrict__ Wr)
{
    if (blockIdx.y == 1) {
        int i4 = blockIdx.x * 256 + threadIdx.x;      // < 3*C*C/4
        int which = i4 / (C_ * C_ / 4);
        int i = (i4 - which * (C_ * C_ / 4)) * 4;
        const float* src = (which == 0) ? Wk : (which == 1) ? Wv : Wr;
        float4 v = *(const float4*)&src[i];
        __half2 h01 = __halves2half2(__float2half_rn(v.x), __float2half_rn(v.y));
        __half2 h23 = __halves2half2(__float2half_rn(v.z), __float2half_rn(v.w));
        *reinterpret_cast<uint2*>(&g_W16[which][i]) =
            make_uint2(*(uint32_t*)&h01, *(uint32_t*)&h23);
        return;
    }

    int idx8 = blockIdx.x * blockDim.x + threadIdx.x;   // < BTC/8
    int c8 = idx8 & 127;
    int bt = idx8 >> 7;
    int t  = bt & (T_ - 1);
    int b  = bt >> 11;
    int c  = c8 * 8;

    int token = tok[bt];
    const float* cur = &emb[(size_t)token * C_ + c];
    const float* prv = (t == 0) ? &xx_init[b * C_ + c]
                                : &emb[(size_t)tok[bt - 1] * C_ + c];

    float4 xc0 = *(const float4*)(cur);
    float4 xc1 = *(const float4*)(cur + 4);
    float4 xp0 = *(const float4*)(prv);
    float4 xp1 = *(const float4*)(prv + 4);

#define MIX8(arr, mixp)  do {                                               \
        float4 m0 = *(const float4*)&(mixp)[c];                             \
        float4 m1 = *(const float4*)&(mixp)[c + 4];                         \
        float v0 = xc0.x * m0.x + xp0.x * (1.0f - m0.x);                    \
        float v1 = xc0.y * m0.y + xp0.y * (1.0f - m0.y);                    \
        float v2 = xc0.z * m0.z + xp0.z * (1.0f - m0.z);                    \
        float v3 = xc0.w * m0.w + xp0.w * (1.0f - m0.w);                    \
        float v4 = xc1.x * m1.x + xp1.x * (1.0f - m1.x);                    \
        float v5 = xc1.y * m1.y + xp1.y * (1.0f - m1.y);                    \
        float v6 = xc1.z * m1.z + xp1.z * (1.0f - m1.z);                    \
        float v7 = xc1.w * m1.w + xp1.w * (1.0f - m1.w);                    \
        __half2 h01 = __halves2half2(__float2half_rn(v0), __float2half_rn(v1)); \
        __half2 h23 = __halves2half2(__float2half_rn(v2), __float2half_rn(v3)); \
        __half2 h45 = __halves2half2(__float2half_rn(v4), __float2half_rn(v5)); \
        __half2 h67 = __halves2half2(__float2half_rn(v6), __float2half_rn(v7)); \
        uint4 pack = make_uint4(*(uint32_t*)&h01, *(uint32_t*)&h23,         \
                                *(uint32_t*)&h45, *(uint32_t*)&h67);        \
        *reinterpret_cast<uint4*>(&(arr)[(size_t)idx8 * 8]) = pack;         \
    } while (0)

    MIX8(g_xk, tmk);
    MIX8(g_xv, tmv);
    MIX8(g_xr, tmr);
#undef MIX8
}

// ---------------------------------------------------------------------------
// K2: fp16 NT GEMM: C[M,N] = A[M,K] * W[N,K]^T  (fp32 accumulate, fp16 out).
// R14 config (best measured): 128x128x64 block, 4 warps (128 thr), warp tile
// 64x64, 3-stage cp.async, 2 CTAs/SM.
// SMEM rows = 128B data + 16B pad (144B) => conflict-free ldmatrix.
// blockIdx.z: 0 -> k, 1 -> v, 2 -> sigmoid -> r
// ---------------------------------------------------------------------------
#define BM 128
#define BN 128
#define BK 64
#define ROWB 144                          // 128 data + 16 pad
#define AT_BYTES (BM * ROWB)              // 18432
#define BT_BYTES (BN * ROWB)              // 18432
#define STAGEB (AT_BYTES + BT_BYTES)      // 36864
#define NSTAGE 3
#define GEMM_SMEM (NSTAGE * STAGEB)       // 110592 (x2 CTAs = 221184)
#define NKT (C_ / BK)                     // 16 K-chunks
#define GTHREADS 128

__global__ __launch_bounds__(GTHREADS, 2)
void gemm_mma_kernel()
{
    extern __shared__ char smem[];
    const uint32_t sb = smem_u32(smem);
    const int tid  = threadIdx.x;
    const int wid  = tid >> 5;          // 0..3
    const int lane = tid & 31;

    const int which = blockIdx.z;
    const int n0 = blockIdx.x * BN;
    const int m0 = blockIdx.y * BM;

    const __half* Ap = (which == 0) ? g_xk : (which == 1) ? g_xv : g_xr;
    const __half* Wp = g_W16[which];
    __half* __restrict__ Cout = (which == 0) ? g_k16 : (which == 1) ? g_v16 : g_r16;

    const char* A_g = (const char*)(Ap + (size_t)m0 * C_);
    const char* W_g = (const char*)(Wp + (size_t)n0 * C_);

    const int warp_m = (wid & 1) * 64;   // 2 warps along M
    const int warp_n = (wid >> 1) * 64;  // 2 warps along N

    float acc[4][8][4];                  // 64x64 warp tile
#pragma unroll
    for (int i = 0; i < 4; i++)
#pragma unroll
        for (int j = 0; j < 8; j++)
#pragma unroll
            for (int q = 0; q < 4; q++) acc[i][j][q] = 0.0f;

    auto issue_stage = [&](int kt, int stg) {
        const int kb = kt * BK * 2;
        uint32_t base = sb + stg * STAGEB;
        for (int g = tid; g < 1024; g += GTHREADS) {
            int r = g >> 3;
            int c = g & 7;
            cpa16(base + r * ROWB + c * 16, A_g + (size_t)r * (C_ * 2) + kb + c * 16);
        }
        for (int g = tid; g < 1024; g += GTHREADS) {
            int r = g >> 3;
            int c = g & 7;
            cpa16(base + AT_BYTES + r * ROWB + c * 16,
                  W_g + (size_t)r * (C_ * 2) + kb + c * 16);
        }
        cpa_commit();
    };

    issue_stage(0, 0);
    issue_stage(1, 1);

    const int l15 = lane & 15;
    const int l7  = lane & 7;
    const int b_rowadd = ((lane >> 4) & 1) * 8 + l7;
    const int b_koff   = ((lane >> 3) & 1) * 16;

    for (int kt = 0; kt < NKT; kt++) {
        if (kt == NKT - 1) cpa_wait0(); else cpa_wait1();
        __syncthreads();
        if (kt + 2 < NKT) issue_stage(kt + 2, (kt + 2) % NSTAGE);

        const uint32_t base = sb + (kt % NSTAGE) * STAGEB;
        const uint32_t ah = base;
        const uint32_t bw = base + AT_BYTES;

#pragma unroll
        for (int ks = 0; ks < 4; ks++) {
            uint32_t af[4][4];
            uint32_t bf[8][2];
            const uint32_t arow = (warp_m + l15) * ROWB + ks * 32 + (lane >> 4) * 16;
#pragma unroll
            for (int mt = 0; mt < 4; mt++)
                ldsm_x4(af[mt][0], af[mt][1], af[mt][2], af[mt][3],
                        ah + arow + mt * (16 * ROWB));
#pragma unroll
            for (int p = 0; p < 4; p++) {
                uint32_t addr = bw + (warp_n + p * 16 + b_rowadd) * ROWB + ks * 32 + b_koff;
                ldsm_x4(bf[2*p][0], bf[2*p][1], bf[2*p+1][0], bf[2*p+1][1], addr);
            }
#pragma unroll
            for (int mt = 0; mt < 4; mt++)
#pragma unroll
                for (int nt = 0; nt < 8; nt++)
                    mma16816(acc[mt][nt][0], acc[mt][nt][1], acc[mt][nt][2], acc[mt][nt][3],
                             af[mt][0], af[mt][1], af[mt][2], af[mt][3],
                             bf[nt][0], bf[nt][1]);
        }
    }

    const int rbase = m0 + warp_m + (lane >> 2);
    const int cbase = n0 + warp_n + (lane & 3) * 2;
#pragma unroll
    for (int mt = 0; mt < 4; mt++) {
#pragma unroll
        for (int nt = 0; nt < 8; nt++) {
            float v0 = acc[mt][nt][0], v1 = acc[mt][nt][1];
            float v2 = acc[mt][nt][2], v3 = acc[mt][nt][3];
            if (which == 2) {
                v0 = 1.0f / (1.0f + __expf(-v0));
                v1 = 1.0f / (1.0f + __expf(-v1));
                v2 = 1.0f / (1.0f + __expf(-v2));
                v3 = 1.0f / (1.0f + __expf(-v3));
            }
            size_t r0 = (size_t)(rbase + mt * 16) * C_ + cbase + nt * 8;
            size_t r1 = r0 + 8 * C_;
            *reinterpret_cast<__half2*>(&Cout[r0]) =
                __halves2half2(__float2half_rn(v0), __float2half_rn(v1));
            *reinterpret_cast<__half2*>(&Cout[r1]) =
                __halves2half2(__float2half_rn(v2), __float2half_rn(v3));
        }
    }
}

// ---------------------------------------------------------------------------
// K3a: chunk-local WKV summaries. 2 channels/thread (ILP=2), half2 loads.
// ---------------------------------------------------------------------------
__global__ __launch_bounds__(256)
void wkv_passA(const float* __restrict__ time_decay)
{
    const int tid = blockIdx.x * blockDim.x + threadIdx.x;  // 0..131071
    const int bc2 = tid & (BC_/2 - 1);       // 0..4095
    const int j   = tid >> 12;               // 0..31
    const int bc  = bc2 * 2;
    const int c   = bc & (C_ - 1);
    const int b   = bc >> 10;

    const float w0 = -expf(time_decay[c]);
    const float w1 = -expf(time_decay[c + 1]);
    float aa0 = 0.0f, bb0 = 0.0f, pp0 = -1e30f;
    float aa1 = 0.0f, bb1 = 0.0f, pp1 = -1e30f;

    const int base = (b * T_ + j * CL) * C_ + c;
#pragma unroll 4
    for (int i = 0; i < CL; i++) {
        __half2 kh = *reinterpret_cast<const __half2*>(&g_k16[base + i * C_]);
        __half2 vh = *reinterpret_cast<const __half2*>(&g_v16[base + i * C_]);
        float2 kf = __half22float2(kh);
        float2 vf = __half22float2(vh);
        {
            float ww2 = pp0 + w0;
            float d2  = ww2 - kf.x;
            float es  = __expf(-fabsf(d2));
            float e1  = (d2 >= 0.0f) ? 1.0f : es;
            float e2  = (d2 >= 0.0f) ? es : 1.0f;
            aa0 = e1 * aa0 + e2 * vf.x;
            bb0 = e1 * bb0 + e2;
            pp0 = fmaxf(ww2, kf.x);
        }
        {
            float ww2 = pp1 + w1;
            float d2  = ww2 - kf.y;
            float es  = __expf(-fabsf(d2));
            float e1  = (d2 >= 0.0f) ? 1.0f : es;
            float e2  = (d2 >= 0.0f) ? es : 1.0f;
            aa1 = e1 * aa1 + e2 * vf.y;
            bb1 = e1 * bb1 + e2;
            pp1 = fmaxf(ww2, kf.y);
        }
    }
    g_chA[j][bc]     = aa0;  g_chA[j][bc + 1] = aa1;
    g_chB[j][bc]     = bb0;  g_chB[j][bc + 1] = bb1;
    g_chP[j][bc]     = pp0;  g_chP[j][bc + 1] = pp1;
}

// ---------------------------------------------------------------------------
// K3b: serial compose over 32 chunk summaries -> incoming state per chunk.
// All chunk summaries preloaded into registers up-front (independent
// addresses, MLP ~96) so the 32-step dependent chain pays ONE memory latency.
// ---------------------------------------------------------------------------
__global__ __launch_bounds__(256)
void wkv_passB(const float* __restrict__ aa_init,
               const float* __restrict__ bb_init,
               const float* __restrict__ pp_init,
               const float* __restrict__ time_decay)
{
    const int bc = blockIdx.x * blockDim.x + threadIdx.x;  // 0..8191
    const int c  = bc & (C_ - 1);

    // preload all chunk summaries (independent loads, fully overlapped)
    float Aj[NCH], Bj[NCH], Pj[NCH];
#pragma unroll
    for (int j = 0; j < NCH; j++) {
        Aj[j] = g_chA[j][bc];
        Bj[j] = g_chB[j][bc];
        Pj[j] = g_chP[j][bc];
    }

    float aa = aa_init[bc], bb = bb_init[bc], pp = pp_init[bc];
    const float Lw = (float)CL * (-expf(time_decay[c]));

#pragma unroll
    for (int j = 0; j < NCH; j++) {
        g_inA[j][bc] = aa;
        g_inB[j][bc] = bb;
        g_inP[j][bc] = pp;
        float q  = pp + Lw;
        float Pn = fmaxf(q, Pj[j]);
        float e1 = __expf(q - Pn);
        float e2 = __expf(Pj[j] - Pn);
        aa = e1 * aa + e2 * Aj[j];
        bb = e1 * bb + e2 * Bj[j];
        pp = Pn;
    }
}

// ---------------------------------------------------------------------------
// K3c: replay each chunk with incoming state; 2 channels/thread, half2 loads.
// ---------------------------------------------------------------------------
__global__ __launch_bounds__(256)
void wkv_passC(const float* __restrict__ time_decay,
               const float* __restrict__ time_first)
{
    const int tid = blockIdx.x * blockDim.x + threadIdx.x;  // 0..131071
    const int bc2 = tid & (BC_/2 - 1);
    const int j   = tid >> 12;
    const int bc  = bc2 * 2;
    const int c   = bc & (C_ - 1);
    const int b   = bc >> 10;

    const float w0 = -expf(time_decay[c]);
    const float w1 = -expf(time_decay[c + 1]);
    const float u0 = time_first[c];
    const float u1 = time_first[c + 1];

    float aa0 = g_inA[j][bc],     bb0 = g_inB[j][bc],     pp0 = g_inP[j][bc];
    float aa1 = g_inA[j][bc + 1], bb1 = g_inB[j][bc + 1], pp1 = g_inP[j][bc + 1];

    float ysum0 = 0.0f, ysum1 = 0.0f;
    float y0 = 0.0f, y1 = 0.0f;

    const int base = (b * T_ + j * CL) * C_ + c;
#pragma unroll 4
    for (int i = 0; i < CL; i++) {
        __half2 kh = *reinterpret_cast<const __half2*>(&g_k16[base + i * C_]);
        __half2 vh = *reinterpret_cast<const __half2*>(&g_v16[base + i * C_]);
        __half2 rh = *reinterpret_cast<const __half2*>(&g_r16[base + i * C_]);
        float2 kf = __half22float2(kh);
        float2 vf = __half22float2(vh);
        float2 rf = __half22float2(rh);
        {
            float ww = u0 + kf.x;
            float d  = pp0 - ww;
            float es = __expf(-fabsf(d));
            float e1 = (d >= 0.0f) ? 1.0f : es;
            float e2 = (d >= 0.0f) ? es : 1.0f;
            y0 = rf.x * __fdividef(e1 * aa0 + e2 * vf.x, e1 * bb0 + e2);
            ysum0 += y0;
            float ww2 = pp0 + w0;
            float d2  = ww2 - kf.x;
            float es2 = __expf(-fabsf(d2));
            float e1b = (d2 >= 0.0f) ? 1.0f : es2;
            float e2b = (d2 >= 0.0f) ? es2 : 1.0f;
            aa0 = e1b * aa0 + e2b * vf.x;
            bb0 = e1b * bb0 + e2b;
            pp0 = fmaxf(ww2, kf.x);
        }
        {
            float ww = u1 + kf.y;
            float d  = pp1 - ww;
            float es = __expf(-fabsf(d));
            float e1 = (d >= 0.0f) ? 1.0f : es;
            float e2 = (d >= 0.0f) ? es : 1.0f;
            y1 = rf.y * __fdividef(e1 * aa1 + e2 * vf.y, e1 * bb1 + e2);
            ysum1 += y1;
            float ww2 = pp1 + w1;
            float d2  = ww2 - kf.y;
            float es2 = __expf(-fabsf(d2));
            float e1b = (d2 >= 0.0f) ? 1.0f : es2;
            float e2b = (d2 >= 0.0f) ? es2 : 1.0f;
            aa1 = e1b * aa1 + e2b * vf.y;
            bb1 = e1b * bb1 + e2b;
            pp1 = fmaxf(ww2, kf.y);
        }
    }
    g_psum[j][bc]     = ysum0;
    g_psum[j][bc + 1] = ysum1;
    if (j == NCH - 1) {
        g_ylast[bc]     = y0;
        g_ylast[bc + 1] = y1;
    }
}

// ---------------------------------------------------------------------------
// K3d: reduce partials -> z = 0.5*(ylast + mean)
// ---------------------------------------------------------------------------
__global__ __launch_bounds__(256)
void wkv_reduce()
{
    const int bc = blockIdx.x * blockDim.x + threadIdx.x;  // 0..8191
    float s = 0.0f;
#pragma unroll
    for (int j = 0; j < NCH; j++) s += g_psum[j][bc];
    g_z[bc] = 0.5f * (g_ylast[bc] + s * (1.0f / (float)T_));
}

// ---------------------------------------------------------------------------
// K4: tiny output GEMM hx[b,d] = sum_c z[b,c] * Wo[d,c]; out = stack([hx,hx])
// ---------------------------------------------------------------------------
__global__ __launch_bounds__(256)
void final_proj_kernel(const float* __restrict__ Wo,
                       float* __restrict__ out)
{
    int gw   = (blockIdx.x * blockDim.x + threadIdx.x) >> 5;
    int lane = threadIdx.x & 31;
    if (gw >= BC_) return;
    int b = gw >> 10;
    int d = gw & (C_ - 1);

    const float* z  = g_z + b * C_;
    const float* wr = Wo + (size_t)d * C_;
    float s = 0.0f;
#pragma unroll 8
    for (int c = lane; c < C_; c += 32)
        s = fmaf(z[c], wr[c], s);
#pragma unroll
    for (int o = 16; o > 0; o >>= 1)
        s += __shfl_xor_sync(0xFFFFFFFFu, s, o);
    if (lane == 0) {
        out[b * C_ + d]       = s;
        out[BC_ + b * C_ + d] = s;
    }
}

// ---------------------------------------------------------------------------
extern "C" void kernel_launch(void* const* d_in, const int* in_sizes, int n_in,
                              void* d_out, int out_size)
{
    const int*   tok  = (const int*)  d_in[0];
    const float* xx   = (const float*)d_in[1];
    const float* aa   = (const float*)d_in[2];
    const float* bb   = (const float*)d_in[3];
    const float* pp   = (const float*)d_in[4];
    const float* emb  = (const float*)d_in[5];
    const float* tmk  = (const float*)d_in[6];
    const float* tmv  = (const float*)d_in[7];
    const float* tmr  = (const float*)d_in[8];
    const float* tdec = (const float*)d_in[9];
    const float* tfir = (const float*)d_in[10];
    const float* Wk   = (const float*)d_in[11];
    const float* Wv   = (const float*)d_in[12];
    const float* Wr   = (const float*)d_in[13];
    const float* Wo   = (const float*)d_in[14];
    float* out = (float*)d_out;

    cudaFuncSetAttribute(gemm_mma_kernel,
                         cudaFuncAttributeMaxDynamicSharedMemorySize, GEMM_SMEM);

    // Fused prep: y=0 -> embed+mix (8192 blocks), y=1 -> weight conv (3072 blocks)
    dim3 pgrid(BTC / 8 / 256, 2);
    prep_kernel<<<pgrid, 256>>>(tok, xx, emb, tmk, tmv, tmr, Wk, Wv, Wr);

    dim3 ggrid(C_ / BN, M_ / BM, 3);   // (8, 128, 3)
    gemm_mma_kernel<<<ggrid, GTHREADS, GEMM_SMEM>>>();

    wkv_passA<<<(NCH * BC_ / 2) / 256, 256>>>(tdec);
    wkv_passB<<<BC_ / 256, 256>>>(aa, bb, pp, tdec);
    wkv_passC<<<(NCH * BC_ / 2) / 256, 256>>>(tdec, tfir);
    wkv_reduce<<<BC_ / 256, 256>>>();

    final_proj_kernel<<<(BC_ * 32) / 256, 256>>>(Wo, out);
}